// round 5
// baseline (speedup 1.0000x reference)
#include <cuda_runtime.h>

typedef unsigned long long u64;

#define BB 4
#define PP 2
#define SS 1024
#define DD 768
#define NHEADS 12
#define HDIM 64
#define RR (BB*PP*SS)       /* 8192 rows of x/q/k/v/z */
#define NQT (SS/64)         /* 16 q-tiles per attention instance */

/* ---- scratch (static device globals; no allocation at launch time) ---- */
__device__ float g_x [RR*DD];
__device__ float g_q [RR*DD];
__device__ float g_k [RR*DD];
__device__ float g_v [RR*DD];
__device__ float g_z [RR*DD];
__device__ float g_wq[DD*DD];
__device__ float g_wk[DD*DD];
__device__ float g_wv[DD*DD];

/* ---- packed f32x2 helpers (FFMA2: 2x fp32 FMA throughput on sm_103a) ---- */
__device__ __forceinline__ u64 pack2(float x, float y){
    u64 r; asm("mov.b64 %0, {%1,%2};" : "=l"(r) : "f"(x), "f"(y)); return r;
}
__device__ __forceinline__ void unpack2(u64 v, float &x, float &y){
    asm("mov.b64 {%0,%1}, %2;" : "=f"(x), "=f"(y) : "l"(v));
}
__device__ __forceinline__ u64 dup2(float x){ return pack2(x, x); }
__device__ __forceinline__ void fma2(u64 &c, u64 a, u64 b){
    asm("fma.rn.f32x2 %0, %1, %2, %0;" : "+l"(c) : "l"(a), "l"(b));
}
__device__ __forceinline__ u64 mul2(u64 a, u64 b){
    u64 r; asm("mul.rn.f32x2 %0, %1, %2;" : "=l"(r) : "l"(a), "l"(b)); return r;
}

/* ---- build x = concat([normalized, alt[:,None]], axis=1) as [8192,768] ---- */
__global__ __launch_bounds__(256) void pack_x_kernel(const float* __restrict__ x0,
                                                     const float* __restrict__ x1)
{
    int i = blockIdx.x * 256 + threadIdx.x;     /* float4 index */
    if (i >= RR*DD/4) return;
    int row = i / (DD/4);
    int c4  = i - row*(DD/4);
    int bp = row >> 10, s = row & 1023;
    int p = bp & 1, b = bp >> 1;
    const float4* src = reinterpret_cast<const float4*>((p ? x1 : x0) + (size_t)(b*SS + s)*DD);
    reinterpret_cast<float4*>(g_x)[i] = src[c4];
}

/* ---- repack W_{Q,K,V} (N,D,H) -> plain row-major [d][n*64+h] ---- */
__global__ __launch_bounds__(256) void repack_w_kernel(const float* __restrict__ wq,
                                                       const float* __restrict__ wk,
                                                       const float* __restrict__ wv)
{
    int i = blockIdx.x * 256 + threadIdx.x;
    if (i >= DD*DD) return;
    int d = i / DD, c = i - d*DD;
    int src = (c >> 6)*(DD*HDIM) + d*HDIM + (c & 63);
    g_wq[i] = wq[src];
    g_wk[i] = wk[src];
    g_wv[i] = wv[src];
}

/* ---- 128x128x16 fp32 GEMM, 8x8 microtile, FFMA2 inner loop.
       C = A(8192x768) @ B(768x768) + bias.  c_is_out=1 remaps rows into
       the (b,14,1024,768) output tensor (slices c=0,1 = old_ablated). ---- */
__global__ __launch_bounds__(256) void sgemm_kernel(const float* __restrict__ A,
                                                    const float* __restrict__ Bm,
                                                    const float* __restrict__ bias,
                                                    float* __restrict__ C,
                                                    int c_is_out)
{
    __shared__ float As[16][132];   /* A transposed: As[k][row] */
    __shared__ float Bs[16][128];   /* Bs[k][col] */

    const int tid = threadIdx.x;
    const int tx = tid & 15, ty = tid >> 4;
    const size_t row0 = (size_t)blockIdx.y * 128;
    const int    col0 = blockIdx.x * 128;

    u64 acc[8][4];
    #pragma unroll
    for (int i = 0; i < 8; ++i)
        #pragma unroll
        for (int j = 0; j < 4; ++j) acc[i][j] = 0ull;

    const int ar = tid >> 2;          /* 0..63 */
    const int ak = (tid & 3) * 4;
    const int bk = tid >> 5;          /* 0..7  */
    const int bc = (tid & 31) * 4;

    for (int k0 = 0; k0 < DD; k0 += 16) {
        float4 a0 = *(const float4*)(A + (row0 + ar     )*DD + k0 + ak);
        float4 a1 = *(const float4*)(A + (row0 + ar + 64)*DD + k0 + ak);
        float4 b0 = *(const float4*)(Bm + (size_t)(k0 + bk    )*DD + col0 + bc);
        float4 b1 = *(const float4*)(Bm + (size_t)(k0 + bk + 8)*DD + col0 + bc);
        __syncthreads();
        As[ak+0][ar]    = a0.x; As[ak+1][ar]    = a0.y; As[ak+2][ar]    = a0.z; As[ak+3][ar]    = a0.w;
        As[ak+0][ar+64] = a1.x; As[ak+1][ar+64] = a1.y; As[ak+2][ar+64] = a1.z; As[ak+3][ar+64] = a1.w;
        *(float4*)&Bs[bk  ][bc] = b0;
        *(float4*)&Bs[bk+8][bc] = b1;
        __syncthreads();
        #pragma unroll
        for (int kk = 0; kk < 16; ++kk) {
            float4 av0 = *(const float4*)&As[kk][ty*8];
            float4 av1 = *(const float4*)&As[kk][ty*8+4];
            float4 bv0 = *(const float4*)&Bs[kk][tx*8];
            float4 bv1 = *(const float4*)&Bs[kk][tx*8+4];
            u64 bb0 = pack2(bv0.x, bv0.y), bb1 = pack2(bv0.z, bv0.w);
            u64 bb2 = pack2(bv1.x, bv1.y), bb3 = pack2(bv1.z, bv1.w);
            float av[8] = {av0.x,av0.y,av0.z,av0.w,av1.x,av1.y,av1.z,av1.w};
            #pragma unroll
            for (int i = 0; i < 8; ++i) {
                u64 ad = dup2(av[i]);
                fma2(acc[i][0], ad, bb0);
                fma2(acc[i][1], ad, bb1);
                fma2(acc[i][2], ad, bb2);
                fma2(acc[i][3], ad, bb3);
            }
        }
    }

    float bv[8];
    #pragma unroll
    for (int j = 0; j < 8; ++j) bv[j] = bias[col0 + tx*8 + j];
    #pragma unroll
    for (int i = 0; i < 8; ++i) {
        size_t rg = row0 + ty*8 + i;
        float* crow;
        if (c_is_out) {
            int bp = (int)(rg >> 10); int q = (int)(rg & 1023);
            int p = bp & 1, b = bp >> 1;
            crow = C + ((size_t)((b*14 + p)*1024 + q))*DD;
        } else {
            crow = C + rg*DD;
        }
        float o[8];
        unpack2(acc[i][0], o[0], o[1]); unpack2(acc[i][1], o[2], o[3]);
        unpack2(acc[i][2], o[4], o[5]); unpack2(acc[i][3], o[6], o[7]);
        float4 s0 = make_float4(o[0]+bv[0], o[1]+bv[1], o[2]+bv[2], o[3]+bv[3]);
        float4 s1 = make_float4(o[4]+bv[4], o[5]+bv[5], o[6]+bv[6], o[7]+bv[7]);
        *(float4*)(crow + col0 + tx*8)     = s0;
        *(float4*)(crow + col0 + tx*8 + 4) = s1;
    }
}

/* ---- streaming-softmax causal attention, fp32, 64-q-row tiles.
       grid (16 qtiles, 12 heads, 8 b*p).  Writes z to g_z[row][n*64+h]. ---- */
__global__ __launch_bounds__(256) void attn_kernel()
{
    __shared__ float Qs [64][64];   /* [h][q], pre-scaled by 1/8 */
    __shared__ float KPs[64][64];   /* K as [h][c]; reused as P[c][q] */
    __shared__ float Vs [64][64];   /* [c][h] */

    const int tid = threadIdx.x;
    const int tx = tid & 15, ty = tid >> 4;
    const int qt = NQT - 1 - (int)blockIdx.x;   /* heavy tiles first */
    const int n  = blockIdx.y;
    const int bp = blockIdx.z;
    const int q0 = qt * 64;

    const float* Qg = g_q + ((size_t)bp*SS + q0)*DD + n*HDIM;
    const float* Kg = g_k + (size_t)bp*SS*DD + n*HDIM;
    const float* Vg = g_v + (size_t)bp*SS*DD + n*HDIM;

    /* load Q tile transposed + scaled */
    {
        int r = tid >> 2, h0 = (tid & 3) * 16;
        #pragma unroll
        for (int g = 0; g < 4; ++g) {
            float4 v = *(const float4*)(Qg + (size_t)r*DD + h0 + g*4);
            Qs[h0+g*4+0][r] = v.x * 0.125f;
            Qs[h0+g*4+1][r] = v.y * 0.125f;
            Qs[h0+g*4+2][r] = v.z * 0.125f;
            Qs[h0+g*4+3][r] = v.w * 0.125f;
        }
    }

    float m_i[4] = {-1e30f, -1e30f, -1e30f, -1e30f};
    float l_i[4] = {0.f, 0.f, 0.f, 0.f};
    u64 z[4][2];
    #pragma unroll
    for (int i = 0; i < 4; ++i) { z[i][0] = 0ull; z[i][1] = 0ull; }

    for (int kt = 0; kt <= qt; ++kt) {
        int k0 = kt * 64;
        __syncthreads();    /* prev PV reads done; also fences Q-load on kt=0 */
        {
            int r = tid >> 2, h0 = (tid & 3) * 16;
            #pragma unroll
            for (int g = 0; g < 4; ++g) {
                float4 kv = *(const float4*)(Kg + (size_t)(k0+r)*DD + h0 + g*4);
                KPs[h0+g*4+0][r] = kv.x;
                KPs[h0+g*4+1][r] = kv.y;
                KPs[h0+g*4+2][r] = kv.z;
                KPs[h0+g*4+3][r] = kv.w;
                float4 vv = *(const float4*)(Vg + (size_t)(k0+r)*DD + h0 + g*4);
                *(float4*)&Vs[r][h0+g*4] = vv;
            }
        }
        __syncthreads();

        /* S = Q K^T : rows ty*4.., cols tx*4.. */
        u64 s2[4][2];
        #pragma unroll
        for (int i = 0; i < 4; ++i) { s2[i][0] = 0ull; s2[i][1] = 0ull; }
        #pragma unroll
        for (int h = 0; h < 64; ++h) {
            float4 aq  = *(const float4*)&Qs [h][ty*4];
            float4 bk4 = *(const float4*)&KPs[h][tx*4];
            u64 b01 = pack2(bk4.x, bk4.y), b23 = pack2(bk4.z, bk4.w);
            u64 d0 = dup2(aq.x); fma2(s2[0][0], d0, b01); fma2(s2[0][1], d0, b23);
            u64 d1 = dup2(aq.y); fma2(s2[1][0], d1, b01); fma2(s2[1][1], d1, b23);
            u64 d2 = dup2(aq.z); fma2(s2[2][0], d2, b01); fma2(s2[2][1], d2, b23);
            u64 d3 = dup2(aq.w); fma2(s2[3][0], d3, b01); fma2(s2[3][1], d3, b23);
        }
        float s[4][4];
        #pragma unroll
        for (int i = 0; i < 4; ++i) {
            unpack2(s2[i][0], s[i][0], s[i][1]);
            unpack2(s2[i][1], s[i][2], s[i][3]);
        }
        if (kt == qt) {
            #pragma unroll
            for (int i = 0; i < 4; ++i)
                #pragma unroll
                for (int j = 0; j < 4; ++j)
                    if (ty*4 + i < tx*4 + j) s[i][j] = -1e30f;
        }

        /* online softmax per q-row (rows on ty, cols spread over 16 tx lanes) */
        float p[4][4];
        #pragma unroll
        for (int i = 0; i < 4; ++i) {
            float mx = fmaxf(fmaxf(s[i][0], s[i][1]), fmaxf(s[i][2], s[i][3]));
            mx = fmaxf(mx, __shfl_xor_sync(0xffffffffu, mx, 1));
            mx = fmaxf(mx, __shfl_xor_sync(0xffffffffu, mx, 2));
            mx = fmaxf(mx, __shfl_xor_sync(0xffffffffu, mx, 4));
            mx = fmaxf(mx, __shfl_xor_sync(0xffffffffu, mx, 8));
            float mnew = fmaxf(m_i[i], mx);
            float al = __expf(m_i[i] - mnew);
            float sum = 0.f;
            #pragma unroll
            for (int j = 0; j < 4; ++j) { p[i][j] = __expf(s[i][j] - mnew); sum += p[i][j]; }
            sum += __shfl_xor_sync(0xffffffffu, sum, 1);
            sum += __shfl_xor_sync(0xffffffffu, sum, 2);
            sum += __shfl_xor_sync(0xffffffffu, sum, 4);
            sum += __shfl_xor_sync(0xffffffffu, sum, 8);
            l_i[i] = l_i[i]*al + sum;
            m_i[i] = mnew;
            u64 al2 = dup2(al);
            z[i][0] = mul2(z[i][0], al2);
            z[i][1] = mul2(z[i][1], al2);
        }

        __syncthreads();    /* all S-readers of KPs done */
        #pragma unroll
        for (int i = 0; i < 4; ++i)
            #pragma unroll
            for (int j = 0; j < 4; ++j)
                KPs[tx*4 + j][ty*4 + i] = p[i][j];   /* P transposed: [k][q] */
        __syncthreads();

        /* z += P @ V : rows ty*4.., h-cols tx*4.. */
        #pragma unroll
        for (int kk = 0; kk < 64; ++kk) {
            float4 pv = *(const float4*)&KPs[kk][ty*4];
            float4 vv = *(const float4*)&Vs [kk][tx*4];
            u64 v01 = pack2(vv.x, vv.y), v23 = pack2(vv.z, vv.w);
            u64 d0 = dup2(pv.x); fma2(z[0][0], d0, v01); fma2(z[0][1], d0, v23);
            u64 d1 = dup2(pv.y); fma2(z[1][0], d1, v01); fma2(z[1][1], d1, v23);
            u64 d2 = dup2(pv.z); fma2(z[2][0], d2, v01); fma2(z[2][1], d2, v23);
            u64 d3 = dup2(pv.w); fma2(z[3][0], d3, v01); fma2(z[3][1], d3, v23);
        }
    }

    #pragma unroll
    for (int i = 0; i < 4; ++i) {
        float inv = 1.0f / l_i[i];
        float o0, o1, o2, o3;
        unpack2(z[i][0], o0, o1);
        unpack2(z[i][1], o2, o3);
        float4 vout = make_float4(o0*inv, o1*inv, o2*inv, o3*inv);
        size_t row = (size_t)bp*SS + q0 + ty*4 + i;
        *(float4*)(g_z + row*DD + n*HDIM + tx*4) = vout;
    }
}

/* ---- per-head delta GEMM:
       out[b,2+head,q,:] = out[b,1,q,:] + (z_{p=0}-z_{p=1})[b,q,head] @ W_O[head]
       grid (6 colblocks, 32 rowblocks of 4096, 12 heads) ---- */
__global__ __launch_bounds__(256) void delta_kernel(const float* __restrict__ Wo,
                                                    float* __restrict__ out)
{
    __shared__ float As[16][132];
    __shared__ float Bs[16][128];

    const int tid = threadIdx.x;
    const int tx = tid & 15, ty = tid >> 4;
    const int head = blockIdx.z;
    const size_t row0 = (size_t)blockIdx.y * 128;   /* over 4096 (b,q) rows */
    const int    col0 = blockIdx.x * 128;
    const int b = (int)(row0 >> 10);
    const float* Bm = Wo + (size_t)head * HDIM * DD;

    u64 acc[8][4];
    #pragma unroll
    for (int i = 0; i < 8; ++i)
        #pragma unroll
        for (int j = 0; j < 4; ++j) acc[i][j] = 0ull;

    const int ar = tid >> 2;
    const int ak = (tid & 3) * 4;
    const int bk = tid >> 5;
    const int bc = (tid & 31) * 4;

    for (int k0 = 0; k0 < HDIM; k0 += 16) {
        int q = ((int)row0 + ar) & 1023;
        size_t z0 = ((size_t)(b*2 + 0)*SS + q)*DD + head*HDIM + k0 + ak;
        size_t z1 = ((size_t)(b*2 + 1)*SS + q)*DD + head*HDIM + k0 + ak;
        float4 p0  = *(const float4*)(g_z + z0);
        float4 p1  = *(const float4*)(g_z + z1);
        float4 p0b = *(const float4*)(g_z + z0 + (size_t)64*DD);
        float4 p1b = *(const float4*)(g_z + z1 + (size_t)64*DD);
        float4 a0 = make_float4(p0.x-p1.x,   p0.y-p1.y,   p0.z-p1.z,   p0.w-p1.w);
        float4 a1 = make_float4(p0b.x-p1b.x, p0b.y-p1b.y, p0b.z-p1b.z, p0b.w-p1b.w);
        float4 b0 = *(const float4*)(Bm + (size_t)(k0 + bk    )*DD + col0 + bc);
        float4 b1 = *(const float4*)(Bm + (size_t)(k0 + bk + 8)*DD + col0 + bc);
        __syncthreads();
        As[ak+0][ar]    = a0.x; As[ak+1][ar]    = a0.y; As[ak+2][ar]    = a0.z; As[ak+3][ar]    = a0.w;
        As[ak+0][ar+64] = a1.x; As[ak+1][ar+64] = a1.y; As[ak+2][ar+64] = a1.z; As[ak+3][ar+64] = a1.w;
        *(float4*)&Bs[bk  ][bc] = b0;
        *(float4*)&Bs[bk+8][bc] = b1;
        __syncthreads();
        #pragma unroll
        for (int kk = 0; kk < 16; ++kk) {
            float4 av0 = *(const float4*)&As[kk][ty*8];
            float4 av1 = *(const float4*)&As[kk][ty*8+4];
            float4 bv0 = *(const float4*)&Bs[kk][tx*8];
            float4 bv1 = *(const float4*)&Bs[kk][tx*8+4];
            u64 bb0 = pack2(bv0.x, bv0.y), bb1 = pack2(bv0.z, bv0.w);
            u64 bb2 = pack2(bv1.x, bv1.y), bb3 = pack2(bv1.z, bv1.w);
            float av[8] = {av0.x,av0.y,av0.z,av0.w,av1.x,av1.y,av1.z,av1.w};
            #pragma unroll
            for (int i = 0; i < 8; ++i) {
                u64 ad = dup2(av[i]);
                fma2(acc[i][0], ad, bb0);
                fma2(acc[i][1], ad, bb1);
                fma2(acc[i][2], ad, bb2);
                fma2(acc[i][3], ad, bb3);
            }
        }
    }

    #pragma unroll
    for (int i = 0; i < 8; ++i) {
        int q = ((int)row0 + ty*8 + i) & 1023;
        const float* base = out + ((size_t)(b*14 + 1)*SS + q)*DD + col0 + tx*8;
        float*       dst  = out + ((size_t)(b*14 + 2 + head)*SS + q)*DD + col0 + tx*8;
        float o[8];
        unpack2(acc[i][0], o[0], o[1]); unpack2(acc[i][1], o[2], o[3]);
        unpack2(acc[i][2], o[4], o[5]); unpack2(acc[i][3], o[6], o[7]);
        float4 b0 = *(const float4*)(base);
        float4 b1 = *(const float4*)(base + 4);
        float4 s0 = make_float4(b0.x+o[0], b0.y+o[1], b0.z+o[2], b0.w+o[3]);
        float4 s1 = make_float4(b1.x+o[4], b1.y+o[5], b1.z+o[6], b1.w+o[7]);
        *(float4*)(dst)     = s0;
        *(float4*)(dst + 4) = s1;
    }
}

extern "C" void kernel_launch(void* const* d_in, const int* in_sizes, int n_in,
                              void* d_out, int out_size)
{
    const float* x0 = (const float*)d_in[0];   /* normalized_resid_pre (4,1,1024,768) */
    const float* x1 = (const float*)d_in[1];   /* alt_normalized_resid_pre (4,1024,768) */
    const float* WQ = (const float*)d_in[2];
    const float* bQ = (const float*)d_in[3];
    const float* WK = (const float*)d_in[4];
    const float* bK = (const float*)d_in[5];
    const float* WV = (const float*)d_in[6];
    const float* bV = (const float*)d_in[7];
    const float* WO = (const float*)d_in[8];   /* (12,64,768) == row-major [768][768] */
    const float* bO = (const float*)d_in[9];
    float* out = (float*)d_out;

    float *gx, *gq, *gk, *gv, *gz, *gwq, *gwk, *gwv;
    cudaGetSymbolAddress((void**)&gx,  g_x);
    cudaGetSymbolAddress((void**)&gq,  g_q);
    cudaGetSymbolAddress((void**)&gk,  g_k);
    cudaGetSymbolAddress((void**)&gv,  g_v);
    cudaGetSymbolAddress((void**)&gz,  g_z);
    cudaGetSymbolAddress((void**)&gwq, g_wq);
    cudaGetSymbolAddress((void**)&gwk, g_wk);
    cudaGetSymbolAddress((void**)&gwv, g_wv);

    pack_x_kernel <<<RR*DD/4/256, 256>>>(x0, x1);
    repack_w_kernel<<<DD*DD/256,   256>>>(WQ, WK, WV);

    dim3 gproj(DD/128, RR/128);                 /* (6, 64) */
    sgemm_kernel<<<gproj, 256>>>(gx, gwq, bQ, gq, 0);
    sgemm_kernel<<<gproj, 256>>>(gx, gwk, bK, gk, 0);
    sgemm_kernel<<<gproj, 256>>>(gx, gwv, bV, gv, 0);

    attn_kernel<<<dim3(NQT, NHEADS, BB*PP), 256>>>();

    sgemm_kernel<<<gproj, 256>>>(gz, WO, bO, out, 1);     /* old_ablated (c=0,1) */

    delta_kernel<<<dim3(DD/128, BB*SS/128, NHEADS), 256>>>(WO, out);
}

// round 7
// speedup vs baseline: 1.3750x; 1.3750x over previous
#include <cuda_runtime.h>
#include <cuda_bf16.h>
#include <cstdint>

typedef unsigned long long u64;

#define BB 4
#define PP 2
#define SS 1024
#define DD 768
#define NHEADS 12
#define HDIM 64
#define RR (BB*PP*SS)       /* 8192 rows of x/q/k/v/z */
#define NQT (SS/64)         /* 16 q-tiles per attention instance */

/* ---- scratch (static device globals; no allocation at launch time) ---- */
__device__ float g_q [RR*DD];
__device__ float g_k [RR*DD];
__device__ float g_v [RR*DD];
__device__ float g_z [RR*DD];
/* bf16 hi/lo split operands for tensor-core GEMMs */
__device__ __align__(16) __nv_bfloat16 g_xh [RR*DD];
__device__ __align__(16) __nv_bfloat16 g_xl [RR*DD];
__device__ __align__(16) __nv_bfloat16 g_zh [RR*DD];
__device__ __align__(16) __nv_bfloat16 g_zl [RR*DD];
__device__ __align__(16) __nv_bfloat16 g_wth[3*DD*DD];   /* Wq,Wk,Wv transposed [n][k], hi */
__device__ __align__(16) __nv_bfloat16 g_wtl[3*DD*DD];   /* lo */
__device__ __align__(16) __nv_bfloat16 g_woth[DD*DD];    /* Wo transposed [n][k], hi */
__device__ __align__(16) __nv_bfloat16 g_wotl[DD*DD];    /* lo */

/* ================= packed f32x2 helpers (FFMA2) ================= */
__device__ __forceinline__ u64 pack2(float x, float y){
    u64 r; asm("mov.b64 %0, {%1,%2};" : "=l"(r) : "f"(x), "f"(y)); return r;
}
__device__ __forceinline__ void unpack2(u64 v, float &x, float &y){
    asm("mov.b64 {%0,%1}, %2;" : "=f"(x), "=f"(y) : "l"(v));
}
__device__ __forceinline__ u64 dup2(float x){ return pack2(x, x); }
__device__ __forceinline__ void fma2(u64 &c, u64 a, u64 b){
    asm("fma.rn.f32x2 %0, %1, %2, %0;" : "+l"(c) : "l"(a), "l"(b));
}
__device__ __forceinline__ u64 mul2(u64 a, u64 b){
    u64 r; asm("mul.rn.f32x2 %0, %1, %2;" : "=l"(r) : "l"(a), "l"(b)); return r;
}

/* ================= warp-level bf16 MMA helpers (baseline PTX, HMMA) ========= */
__device__ __forceinline__ uint32_t smem_u32(const void* p){
    uint32_t a;
    asm("{ .reg .u64 t; cvta.to.shared.u64 t, %1; cvt.u32.u64 %0, t; }" : "=r"(a) : "l"(p));
    return a;
}
__device__ __forceinline__ void ldm_x4(uint32_t* r, uint32_t addr){
    asm volatile("ldmatrix.sync.aligned.m8n8.x4.shared.b16 {%0,%1,%2,%3}, [%4];"
        : "=r"(r[0]),"=r"(r[1]),"=r"(r[2]),"=r"(r[3]) : "r"(addr));
}
__device__ __forceinline__ void mma_bf16(float* d, const uint32_t* a, uint32_t b0, uint32_t b1){
    asm volatile("mma.sync.aligned.m16n8k16.row.col.f32.bf16.bf16.f32 "
        "{%0,%1,%2,%3}, {%4,%5,%6,%7}, {%8,%9}, {%0,%1,%2,%3};"
        : "+f"(d[0]),"+f"(d[1]),"+f"(d[2]),"+f"(d[3])
        : "r"(a[0]),"r"(a[1]),"r"(a[2]),"r"(a[3]), "r"(b0),"r"(b1));
}

__device__ __forceinline__ void split_bf16(float x, __nv_bfloat16 &h, __nv_bfloat16 &l){
    h = __float2bfloat16(x);
    l = __float2bfloat16(x - __bfloat162float(h));
}

/* ---- build x = concat([normalized, alt[:,None]], axis=1) directly as hi/lo bf16 ---- */
__global__ __launch_bounds__(256) void pack_x_kernel(const float* __restrict__ x0,
                                                     const float* __restrict__ x1)
{
    int i = blockIdx.x * 256 + threadIdx.x;     /* float4 index */
    if (i >= RR*DD/4) return;
    int row = i / (DD/4);
    int c4  = i - row*(DD/4);
    int bp = row >> 10, s = row & 1023;
    int p = bp & 1, b = bp >> 1;
    const float4* src = reinterpret_cast<const float4*>((p ? x1 : x0) + (size_t)(b*SS + s)*DD);
    float4 v = src[c4];
    __nv_bfloat16 h0,h1,h2,h3,l0,l1,l2,l3;
    split_bf16(v.x,h0,l0); split_bf16(v.y,h1,l1); split_bf16(v.z,h2,l2); split_bf16(v.w,h3,l3);
    __nv_bfloat162* dh = reinterpret_cast<__nv_bfloat162*>(g_xh) + i*2;
    __nv_bfloat162* dl = reinterpret_cast<__nv_bfloat162*>(g_xl) + i*2;
    dh[0] = __nv_bfloat162(h0,h1); dh[1] = __nv_bfloat162(h2,h3);
    dl[0] = __nv_bfloat162(l0,l1); dl[1] = __nv_bfloat162(l2,l3);
}

/* ---- convert z (fp32) -> hi/lo bf16 ---- */
__global__ __launch_bounds__(256) void convert_z_kernel()
{
    int i = blockIdx.x * 256 + threadIdx.x;
    if (i >= RR*DD/4) return;
    float4 v = reinterpret_cast<const float4*>(g_z)[i];
    __nv_bfloat16 h0,h1,h2,h3,l0,l1,l2,l3;
    split_bf16(v.x,h0,l0); split_bf16(v.y,h1,l1); split_bf16(v.z,h2,l2); split_bf16(v.w,h3,l3);
    __nv_bfloat162* dh = reinterpret_cast<__nv_bfloat162*>(g_zh) + i*2;
    __nv_bfloat162* dl = reinterpret_cast<__nv_bfloat162*>(g_zl) + i*2;
    dh[0] = __nv_bfloat162(h0,h1); dh[1] = __nv_bfloat162(h2,h3);
    dl[0] = __nv_bfloat162(l0,l1); dl[1] = __nv_bfloat162(l2,l3);
}

/* ---- repack weights to B-operand layout [n][k] and split hi/lo.
       Wq/k/v: (12,768,64) -> Bt[n=head*64+h][k=d].  Wo: [k][n] -> Bt[n][k]. ---- */
__global__ __launch_bounds__(256) void repack_w_kernel(const float* __restrict__ wq,
                                                       const float* __restrict__ wk,
                                                       const float* __restrict__ wv,
                                                       const float* __restrict__ wo)
{
    int i = blockIdx.x * 256 + threadIdx.x;
    if (i >= DD*DD) return;
    int n = i / DD, k = i - n*DD;
    int srcqkv = (n >> 6)*(DD*HDIM) + k*HDIM + (n & 63);
    __nv_bfloat16 h, l;
    split_bf16(wq[srcqkv], h, l); g_wth[i]          = h; g_wtl[i]          = l;
    split_bf16(wk[srcqkv], h, l); g_wth[DD*DD+i]    = h; g_wtl[DD*DD+i]    = l;
    split_bf16(wv[srcqkv], h, l); g_wth[2*DD*DD+i]  = h; g_wtl[2*DD*DD+i]  = l;
    split_bf16(wo[(size_t)k*DD + n], h, l); g_woth[i] = h; g_wotl[i] = l;
}

/* ---- warp-MMA split-bf16 GEMM: C[8192x768] = A @ B^T(stored [n][k]) + bias.
       CTA tile 128x128, 8 warps in 2x4 (64x32 each), K-slab 32.
       3 mma products per fragment (hi*hi + hi*lo + lo*hi).
       c_is_out=1 remaps rows into (b,14,1024,768) output (slices 0,1). ---- */
#define SPAD 40   /* bf16 row stride in smem: 80B -> conflict-free ldmatrix */
__global__ __launch_bounds__(256) void gemm_mma(const __nv_bfloat16* __restrict__ Ah,
                                                const __nv_bfloat16* __restrict__ Al,
                                                const __nv_bfloat16* __restrict__ Bh,
                                                const __nv_bfloat16* __restrict__ Bl,
                                                const float* __restrict__ bias,
                                                float* __restrict__ C,
                                                int c_is_out)
{
    __shared__ __nv_bfloat16 sAh[128][SPAD];
    __shared__ __nv_bfloat16 sAl[128][SPAD];
    __shared__ __nv_bfloat16 sBh[128][SPAD];
    __shared__ __nv_bfloat16 sBl[128][SPAD];

    const int tid  = threadIdx.x;
    const int wid  = tid >> 5, lane = tid & 31;
    const int wm   = (wid >> 2) * 64;       /* warp row base within tile   */
    const int wn   = (wid & 3) * 32;        /* warp col base within tile   */
    const size_t row0 = (size_t)blockIdx.y * 128;
    const int    n0   = blockIdx.x * 128;

    float acc[4][4][4];
    #pragma unroll
    for (int mi = 0; mi < 4; ++mi)
        #pragma unroll
        for (int ni = 0; ni < 4; ++ni)
            #pragma unroll
            for (int e = 0; e < 4; ++e) acc[mi][ni][e] = 0.f;

    const int lrow = lane & 15, lcol = (lane >> 4) * 8;

    for (int k0 = 0; k0 < DD; k0 += 32) {
        __syncthreads();
        #pragma unroll
        for (int t = 0; t < 2; ++t) {
            int idx = tid + t*256;          /* 0..511: row r=idx>>2, 16B chunk c=idx&3 */
            int r = idx >> 2, c = idx & 3;
            size_t ga = (row0 + r)*DD + k0 + c*8;
            size_t gb = (size_t)(n0 + r)*DD + k0 + c*8;
            *(uint4*)&sAh[r][c*8] = *(const uint4*)(Ah + ga);
            *(uint4*)&sAl[r][c*8] = *(const uint4*)(Al + ga);
            *(uint4*)&sBh[r][c*8] = *(const uint4*)(Bh + gb);
            *(uint4*)&sBl[r][c*8] = *(const uint4*)(Bl + gb);
        }
        __syncthreads();

        #pragma unroll
        for (int ks = 0; ks < 2; ++ks) {
            const int kb = ks*16 + lcol;
            uint32_t ah[4][4], al[4][4], bh[2][4], bl[2][4];
            #pragma unroll
            for (int mi = 0; mi < 4; ++mi) {
                ldm_x4(ah[mi], smem_u32(&sAh[wm + mi*16 + lrow][kb]));
                ldm_x4(al[mi], smem_u32(&sAl[wm + mi*16 + lrow][kb]));
            }
            #pragma unroll
            for (int g = 0; g < 2; ++g) {
                ldm_x4(bh[g], smem_u32(&sBh[wn + g*16 + lrow][kb]));
                ldm_x4(bl[g], smem_u32(&sBl[wn + g*16 + lrow][kb]));
            }
            #pragma unroll
            for (int mi = 0; mi < 4; ++mi)
                #pragma unroll
                for (int ni = 0; ni < 4; ++ni) {
                    const int g = ni >> 1, h = ni & 1;   /* n8 tile h of n16 group g */
                    mma_bf16(acc[mi][ni], ah[mi], bh[g][h], bh[g][h+2]);
                    mma_bf16(acc[mi][ni], ah[mi], bl[g][h], bl[g][h+2]);
                    mma_bf16(acc[mi][ni], al[mi], bh[g][h], bh[g][h+2]);
                }
        }
    }

    /* epilogue: thread holds rows (wm+mi*16 + lane/4, +8), cols wn+ni*8+(lane%4)*2 */
    const int r_lo = lane >> 2, cpair = (lane & 3) * 2;
    #pragma unroll
    for (int mi = 0; mi < 4; ++mi) {
        size_t rg0 = row0 + wm + mi*16 + r_lo;
        size_t rg1 = rg0 + 8;
        float *crow0, *crow1;
        if (c_is_out) {
            int bp = (int)(rg0 >> 10); int q0r = (int)(rg0 & 1023);
            int p = bp & 1, b = bp >> 1;
            crow0 = C + ((size_t)((b*14 + p)*1024 + q0r))*DD;
            bp = (int)(rg1 >> 10); q0r = (int)(rg1 & 1023);
            p = bp & 1; b = bp >> 1;
            crow1 = C + ((size_t)((b*14 + p)*1024 + q0r))*DD;
        } else {
            crow0 = C + rg0*DD;
            crow1 = C + rg1*DD;
        }
        #pragma unroll
        for (int ni = 0; ni < 4; ++ni) {
            int col = n0 + wn + ni*8 + cpair;
            float2 v0 = make_float2(acc[mi][ni][0] + bias[col], acc[mi][ni][1] + bias[col+1]);
            float2 v1 = make_float2(acc[mi][ni][2] + bias[col], acc[mi][ni][3] + bias[col+1]);
            *(float2*)(crow0 + col) = v0;
            *(float2*)(crow1 + col) = v1;
        }
    }
}

/* ---- streaming-softmax causal attention, fp32, 64-q-row tiles (unchanged) ---- */
__global__ __launch_bounds__(256) void attn_kernel()
{
    __shared__ float Qs [64][64];
    __shared__ float KPs[64][64];
    __shared__ float Vs [64][64];

    const int tid = threadIdx.x;
    const int tx = tid & 15, ty = tid >> 4;
    const int qt = NQT - 1 - (int)blockIdx.x;
    const int n  = blockIdx.y;
    const int bp = blockIdx.z;
    const int q0 = qt * 64;

    const float* Qg = g_q + ((size_t)bp*SS + q0)*DD + n*HDIM;
    const float* Kg = g_k + (size_t)bp*SS*DD + n*HDIM;
    const float* Vg = g_v + (size_t)bp*SS*DD + n*HDIM;

    {
        int r = tid >> 2, h0 = (tid & 3) * 16;
        #pragma unroll
        for (int g = 0; g < 4; ++g) {
            float4 v = *(const float4*)(Qg + (size_t)r*DD + h0 + g*4);
            Qs[h0+g*4+0][r] = v.x * 0.125f;
            Qs[h0+g*4+1][r] = v.y * 0.125f;
            Qs[h0+g*4+2][r] = v.z * 0.125f;
            Qs[h0+g*4+3][r] = v.w * 0.125f;
        }
    }

    float m_i[4] = {-1e30f, -1e30f, -1e30f, -1e30f};
    float l_i[4] = {0.f, 0.f, 0.f, 0.f};
    u64 z[4][2];
    #pragma unroll
    for (int i = 0; i < 4; ++i) { z[i][0] = 0ull; z[i][1] = 0ull; }

    for (int kt = 0; kt <= qt; ++kt) {
        int k0 = kt * 64;
        __syncthreads();
        {
            int r = tid >> 2, h0 = (tid & 3) * 16;
            #pragma unroll
            for (int g = 0; g < 4; ++g) {
                float4 kv = *(const float4*)(Kg + (size_t)(k0+r)*DD + h0 + g*4);
                KPs[h0+g*4+0][r] = kv.x;
                KPs[h0+g*4+1][r] = kv.y;
                KPs[h0+g*4+2][r] = kv.z;
                KPs[h0+g*4+3][r] = kv.w;
                float4 vv = *(const float4*)(Vg + (size_t)(k0+r)*DD + h0 + g*4);
                *(float4*)&Vs[r][h0+g*4] = vv;
            }
        }
        __syncthreads();

        u64 s2[4][2];
        #pragma unroll
        for (int i = 0; i < 4; ++i) { s2[i][0] = 0ull; s2[i][1] = 0ull; }
        #pragma unroll
        for (int h = 0; h < 64; ++h) {
            float4 aq  = *(const float4*)&Qs [h][ty*4];
            float4 bk4 = *(const float4*)&KPs[h][tx*4];
            u64 b01 = pack2(bk4.x, bk4.y), b23 = pack2(bk4.z, bk4.w);
            u64 d0 = dup2(aq.x); fma2(s2[0][0], d0, b01); fma2(s2[0][1], d0, b23);
            u64 d1 = dup2(aq.y); fma2(s2[1][0], d1, b01); fma2(s2[1][1], d1, b23);
            u64 d2 = dup2(aq.z); fma2(s2[2][0], d2, b01); fma2(s2[2][1], d2, b23);
            u64 d3 = dup2(aq.w); fma2(s2[3][0], d3, b01); fma2(s2[3][1], d3, b23);
        }
        float s[4][4];
        #pragma unroll
        for (int i = 0; i < 4; ++i) {
            unpack2(s2[i][0], s[i][0], s[i][1]);
            unpack2(s2[i][1], s[i][2], s[i][3]);
        }
        if (kt == qt) {
            #pragma unroll
            for (int i = 0; i < 4; ++i)
                #pragma unroll
                for (int j = 0; j < 4; ++j)
                    if (ty*4 + i < tx*4 + j) s[i][j] = -1e30f;
        }

        float p[4][4];
        #pragma unroll
        for (int i = 0; i < 4; ++i) {
            float mx = fmaxf(fmaxf(s[i][0], s[i][1]), fmaxf(s[i][2], s[i][3]));
            mx = fmaxf(mx, __shfl_xor_sync(0xffffffffu, mx, 1));
            mx = fmaxf(mx, __shfl_xor_sync(0xffffffffu, mx, 2));
            mx = fmaxf(mx, __shfl_xor_sync(0xffffffffu, mx, 4));
            mx = fmaxf(mx, __shfl_xor_sync(0xffffffffu, mx, 8));
            float mnew = fmaxf(m_i[i], mx);
            float al = __expf(m_i[i] - mnew);
            float sum = 0.f;
            #pragma unroll
            for (int j = 0; j < 4; ++j) { p[i][j] = __expf(s[i][j] - mnew); sum += p[i][j]; }
            sum += __shfl_xor_sync(0xffffffffu, sum, 1);
            sum += __shfl_xor_sync(0xffffffffu, sum, 2);
            sum += __shfl_xor_sync(0xffffffffu, sum, 4);
            sum += __shfl_xor_sync(0xffffffffu, sum, 8);
            l_i[i] = l_i[i]*al + sum;
            m_i[i] = mnew;
            u64 al2 = dup2(al);
            z[i][0] = mul2(z[i][0], al2);
            z[i][1] = mul2(z[i][1], al2);
        }

        __syncthreads();
        #pragma unroll
        for (int i = 0; i < 4; ++i)
            #pragma unroll
            for (int j = 0; j < 4; ++j)
                KPs[tx*4 + j][ty*4 + i] = p[i][j];
        __syncthreads();

        #pragma unroll
        for (int kk = 0; kk < 64; ++kk) {
            float4 pv = *(const float4*)&KPs[kk][ty*4];
            float4 vv = *(const float4*)&Vs [kk][tx*4];
            u64 v01 = pack2(vv.x, vv.y), v23 = pack2(vv.z, vv.w);
            u64 d0 = dup2(pv.x); fma2(z[0][0], d0, v01); fma2(z[0][1], d0, v23);
            u64 d1 = dup2(pv.y); fma2(z[1][0], d1, v01); fma2(z[1][1], d1, v23);
            u64 d2 = dup2(pv.z); fma2(z[2][0], d2, v01); fma2(z[2][1], d2, v23);
            u64 d3 = dup2(pv.w); fma2(z[3][0], d3, v01); fma2(z[3][1], d3, v23);
        }
    }

    #pragma unroll
    for (int i = 0; i < 4; ++i) {
        float inv = 1.0f / l_i[i];
        float o0, o1, o2, o3;
        unpack2(z[i][0], o0, o1);
        unpack2(z[i][1], o2, o3);
        float4 vout = make_float4(o0*inv, o1*inv, o2*inv, o3*inv);
        size_t row = (size_t)bp*SS + q0 + ty*4 + i;
        *(float4*)(g_z + row*DD + n*HDIM + tx*4) = vout;
    }
}

/* ---- per-head delta GEMM (FFMA2, unchanged):
       out[b,2+head,q,:] = out[b,1,q,:] + (z_{p=0}-z_{p=1})[b,q,head] @ W_O[head] ---- */
__global__ __launch_bounds__(256) void delta_kernel(const float* __restrict__ Wo,
                                                    float* __restrict__ out)
{
    __shared__ float As[16][132];
    __shared__ float Bs[16][128];

    const int tid = threadIdx.x;
    const int tx = tid & 15, ty = tid >> 4;
    const int head = blockIdx.z;
    const size_t row0 = (size_t)blockIdx.y * 128;
    const int    col0 = blockIdx.x * 128;
    const int b = (int)(row0 >> 10);
    const float* Bm = Wo + (size_t)head * HDIM * DD;

    u64 acc[8][4];
    #pragma unroll
    for (int i = 0; i < 8; ++i)
        #pragma unroll
        for (int j = 0; j < 4; ++j) acc[i][j] = 0ull;

    const int ar = tid >> 2;
    const int ak = (tid & 3) * 4;
    const int bk = tid >> 5;
    const int bc = (tid & 31) * 4;

    for (int k0 = 0; k0 < HDIM; k0 += 16) {
        int q = ((int)row0 + ar) & 1023;
        size_t z0 = ((size_t)(b*2 + 0)*SS + q)*DD + head*HDIM + k0 + ak;
        size_t z1 = ((size_t)(b*2 + 1)*SS + q)*DD + head*HDIM + k0 + ak;
        float4 p0  = *(const float4*)(g_z + z0);
        float4 p1  = *(const float4*)(g_z + z1);
        float4 p0b = *(const float4*)(g_z + z0 + (size_t)64*DD);
        float4 p1b = *(const float4*)(g_z + z1 + (size_t)64*DD);
        float4 a0 = make_float4(p0.x-p1.x,   p0.y-p1.y,   p0.z-p1.z,   p0.w-p1.w);
        float4 a1 = make_float4(p0b.x-p1b.x, p0b.y-p1b.y, p0b.z-p1b.z, p0b.w-p1b.w);
        float4 b0 = *(const float4*)(Bm + (size_t)(k0 + bk    )*DD + col0 + bc);
        float4 b1 = *(const float4*)(Bm + (size_t)(k0 + bk + 8)*DD + col0 + bc);
        __syncthreads();
        As[ak+0][ar]    = a0.x; As[ak+1][ar]    = a0.y; As[ak+2][ar]    = a0.z; As[ak+3][ar]    = a0.w;
        As[ak+0][ar+64] = a1.x; As[ak+1][ar+64] = a1.y; As[ak+2][ar+64] = a1.z; As[ak+3][ar+64] = a1.w;
        *(float4*)&Bs[bk  ][bc] = b0;
        *(float4*)&Bs[bk+8][bc] = b1;
        __syncthreads();
        #pragma unroll
        for (int kk = 0; kk < 16; ++kk) {
            float4 av0 = *(const float4*)&As[kk][ty*8];
            float4 av1 = *(const float4*)&As[kk][ty*8+4];
            float4 bv0 = *(const float4*)&Bs[kk][tx*8];
            float4 bv1 = *(const float4*)&Bs[kk][tx*8+4];
            u64 bb0 = pack2(bv0.x, bv0.y), bb1 = pack2(bv0.z, bv0.w);
            u64 bb2 = pack2(bv1.x, bv1.y), bb3 = pack2(bv1.z, bv1.w);
            float av[8] = {av0.x,av0.y,av0.z,av0.w,av1.x,av1.y,av1.z,av1.w};
            #pragma unroll
            for (int i = 0; i < 8; ++i) {
                u64 ad = dup2(av[i]);
                fma2(acc[i][0], ad, bb0);
                fma2(acc[i][1], ad, bb1);
                fma2(acc[i][2], ad, bb2);
                fma2(acc[i][3], ad, bb3);
            }
        }
    }

    #pragma unroll
    for (int i = 0; i < 8; ++i) {
        int q = ((int)row0 + ty*8 + i) & 1023;
        const float* base = out + ((size_t)(b*14 + 1)*SS + q)*DD + col0 + tx*8;
        float*       dst  = out + ((size_t)(b*14 + 2 + head)*SS + q)*DD + col0 + tx*8;
        float o[8];
        unpack2(acc[i][0], o[0], o[1]); unpack2(acc[i][1], o[2], o[3]);
        unpack2(acc[i][2], o[4], o[5]); unpack2(acc[i][3], o[6], o[7]);
        float4 b0 = *(const float4*)(base);
        float4 b1 = *(const float4*)(base + 4);
        float4 s0 = make_float4(b0.x+o[0], b0.y+o[1], b0.z+o[2], b0.w+o[3]);
        float4 s1 = make_float4(b1.x+o[4], b1.y+o[5], b1.z+o[6], b1.w+o[7]);
        *(float4*)(dst)     = s0;
        *(float4*)(dst + 4) = s1;
    }
}

extern "C" void kernel_launch(void* const* d_in, const int* in_sizes, int n_in,
                              void* d_out, int out_size)
{
    const float* x0 = (const float*)d_in[0];
    const float* x1 = (const float*)d_in[1];
    const float* WQ = (const float*)d_in[2];
    const float* bQ = (const float*)d_in[3];
    const float* WK = (const float*)d_in[4];
    const float* bK = (const float*)d_in[5];
    const float* WV = (const float*)d_in[6];
    const float* bV = (const float*)d_in[7];
    const float* WO = (const float*)d_in[8];
    const float* bO = (const float*)d_in[9];
    float* out = (float*)d_out;

    float *gq, *gk, *gv;
    __nv_bfloat16 *gxh, *gxl, *gzh, *gzl, *gwth, *gwtl, *gwoth, *gwotl;
    cudaGetSymbolAddress((void**)&gq,   g_q);
    cudaGetSymbolAddress((void**)&gk,   g_k);
    cudaGetSymbolAddress((void**)&gv,   g_v);
    cudaGetSymbolAddress((void**)&gxh,  g_xh);
    cudaGetSymbolAddress((void**)&gxl,  g_xl);
    cudaGetSymbolAddress((void**)&gzh,  g_zh);
    cudaGetSymbolAddress((void**)&gzl,  g_zl);
    cudaGetSymbolAddress((void**)&gwth, g_wth);
    cudaGetSymbolAddress((void**)&gwtl, g_wtl);
    cudaGetSymbolAddress((void**)&gwoth, g_woth);
    cudaGetSymbolAddress((void**)&gwotl, g_wotl);

    pack_x_kernel  <<<RR*DD/4/256, 256>>>(x0, x1);
    repack_w_kernel<<<DD*DD/256,   256>>>(WQ, WK, WV, WO);

    dim3 gproj(DD/128, RR/128);     /* (6, 64) */
    gemm_mma<<<gproj, 256>>>(gxh, gxl, gwth,           gwtl,           bQ, gq, 0);
    gemm_mma<<<gproj, 256>>>(gxh, gxl, gwth + DD*DD,   gwtl + DD*DD,   bK, gk, 0);
    gemm_mma<<<gproj, 256>>>(gxh, gxl, gwth + 2*DD*DD, gwtl + 2*DD*DD, bV, gv, 0);

    attn_kernel<<<dim3(NQT, NHEADS, BB*PP), 256>>>();

    convert_z_kernel<<<RR*DD/4/256, 256>>>();
    gemm_mma<<<gproj, 256>>>(gzh, gzl, gwoth, gwotl, bO, out, 1);

    delta_kernel<<<dim3(DD/128, BB*SS/128, NHEADS), 256>>>(WO, out);
}

// round 13
// speedup vs baseline: 1.8977x; 1.3801x over previous
#include <cuda_runtime.h>
#include <cuda_bf16.h>
#include <cstdint>

typedef unsigned long long u64;

#define BB 4
#define PP 2
#define SS 1024
#define DD 768
#define NHEADS 12
#define HDIM 64
#define RR (BB*PP*SS)       /* 8192 rows */

/* ---- scratch (static device globals) ---- */
__device__ float g_z [RR*DD];
__device__ __align__(16) __nv_bfloat16 g_xh [RR*DD];
__device__ __align__(16) __nv_bfloat16 g_xl [RR*DD];
__device__ __align__(16) __nv_bfloat16 g_qh [RR*DD];
__device__ __align__(16) __nv_bfloat16 g_ql [RR*DD];
__device__ __align__(16) __nv_bfloat16 g_kh [RR*DD];
__device__ __align__(16) __nv_bfloat16 g_kl [RR*DD];
__device__ __align__(16) __nv_bfloat16 g_vh [RR*DD];
__device__ __align__(16) __nv_bfloat16 g_vl [RR*DD];
__device__ __align__(16) __nv_bfloat16 g_zh [RR*DD];
__device__ __align__(16) __nv_bfloat16 g_zl [RR*DD];
__device__ __align__(16) __nv_bfloat16 g_wth[3*DD*DD];   /* Wq,Wk,Wv as [n][k], hi */
__device__ __align__(16) __nv_bfloat16 g_wtl[3*DD*DD];
__device__ __align__(16) __nv_bfloat16 g_woth[DD*DD];    /* Wo as [n][k], hi */
__device__ __align__(16) __nv_bfloat16 g_wotl[DD*DD];

/* ================= packed f32x2 helpers ================= */
__device__ __forceinline__ u64 pack2(float x, float y){
    u64 r; asm("mov.b64 %0, {%1,%2};" : "=l"(r) : "f"(x), "f"(y)); return r;
}
__device__ __forceinline__ void unpack2(u64 v, float &x, float &y){
    asm("mov.b64 {%0,%1}, %2;" : "=f"(x), "=f"(y) : "l"(v));
}
__device__ __forceinline__ u64 dup2(float x){ return pack2(x, x); }
__device__ __forceinline__ void fma2(u64 &c, u64 a, u64 b){
    asm("fma.rn.f32x2 %0, %1, %2, %0;" : "+l"(c) : "l"(a), "l"(b));
}

/* ================= warp-level bf16 MMA helpers ================= */
__device__ __forceinline__ uint32_t smem_u32(const void* p){
    uint32_t a;
    asm("{ .reg .u64 t; cvta.to.shared.u64 t, %1; cvt.u32.u64 %0, t; }" : "=r"(a) : "l"(p));
    return a;
}
__device__ __forceinline__ void ldm_x4(uint32_t* r, uint32_t addr){
    asm volatile("ldmatrix.sync.aligned.m8n8.x4.shared.b16 {%0,%1,%2,%3}, [%4];"
        : "=r"(r[0]),"=r"(r[1]),"=r"(r[2]),"=r"(r[3]) : "r"(addr));
}
__device__ __forceinline__ void ldm_x4_t(uint32_t* r, uint32_t addr){
    asm volatile("ldmatrix.sync.aligned.m8n8.x4.trans.shared.b16 {%0,%1,%2,%3}, [%4];"
        : "=r"(r[0]),"=r"(r[1]),"=r"(r[2]),"=r"(r[3]) : "r"(addr));
}
__device__ __forceinline__ void mma_bf16(float* d, const uint32_t* a, uint32_t b0, uint32_t b1){
    asm volatile("mma.sync.aligned.m16n8k16.row.col.f32.bf16.bf16.f32 "
        "{%0,%1,%2,%3}, {%4,%5,%6,%7}, {%8,%9}, {%0,%1,%2,%3};"
        : "+f"(d[0]),"+f"(d[1]),"+f"(d[2]),"+f"(d[3])
        : "r"(a[0]),"r"(a[1]),"r"(a[2]),"r"(a[3]), "r"(b0),"r"(b1));
}

__device__ __forceinline__ void split_bf16(float x, __nv_bfloat16 &h, __nv_bfloat16 &l){
    h = __float2bfloat16(x);
    l = __float2bfloat16(x - __bfloat162float(h));
}
__device__ __forceinline__ uint32_t pack_bf2(__nv_bfloat16 lo, __nv_bfloat16 hi){
    return (uint32_t)__bfloat16_as_ushort(lo) | ((uint32_t)__bfloat16_as_ushort(hi) << 16);
}

/* ---- build x = concat as hi/lo bf16 ---- */
__global__ __launch_bounds__(256) void pack_x_kernel(const float* __restrict__ x0,
                                                     const float* __restrict__ x1)
{
    int i = blockIdx.x * 256 + threadIdx.x;
    if (i >= RR*DD/4) return;
    int row = i / (DD/4);
    int c4  = i - row*(DD/4);
    int bp = row >> 10, s = row & 1023;
    int p = bp & 1, b = bp >> 1;
    const float4* src = reinterpret_cast<const float4*>((p ? x1 : x0) + (size_t)(b*SS + s)*DD);
    float4 v = src[c4];
    __nv_bfloat16 h0,h1,h2,h3,l0,l1,l2,l3;
    split_bf16(v.x,h0,l0); split_bf16(v.y,h1,l1); split_bf16(v.z,h2,l2); split_bf16(v.w,h3,l3);
    __nv_bfloat162* dh = reinterpret_cast<__nv_bfloat162*>(g_xh) + i*2;
    __nv_bfloat162* dl = reinterpret_cast<__nv_bfloat162*>(g_xl) + i*2;
    dh[0] = __nv_bfloat162(h0,h1); dh[1] = __nv_bfloat162(h2,h3);
    dl[0] = __nv_bfloat162(l0,l1); dl[1] = __nv_bfloat162(l2,l3);
}

/* ---- repack weights to [n][k] hi/lo ---- */
__global__ __launch_bounds__(256) void repack_w_kernel(const float* __restrict__ wq,
                                                       const float* __restrict__ wk,
                                                       const float* __restrict__ wv,
                                                       const float* __restrict__ wo)
{
    int i = blockIdx.x * 256 + threadIdx.x;
    if (i >= DD*DD) return;
    int n = i / DD, k = i - n*DD;
    int srcqkv = (n >> 6)*(DD*HDIM) + k*HDIM + (n & 63);
    __nv_bfloat16 h, l;
    split_bf16(wq[srcqkv], h, l); g_wth[i]          = h; g_wtl[i]          = l;
    split_bf16(wk[srcqkv], h, l); g_wth[DD*DD+i]    = h; g_wtl[DD*DD+i]    = l;
    split_bf16(wv[srcqkv], h, l); g_wth[2*DD*DD+i]  = h; g_wtl[2*DD*DD+i]  = l;
    split_bf16(wo[(size_t)k*DD + n], h, l); g_woth[i] = h; g_wotl[i] = l;
}

/* ---- warp-MMA split-bf16 GEMM, 128x128 tile, K-slab 32.
       mode 0: write (acc+bias)*scale split into Ch/Cl.
       mode 1: write fp32 acc+bias into (b,14,1024,768) remapped C. ---- */
#define SPAD 40
__global__ __launch_bounds__(256) void gemm_mma(const __nv_bfloat16* __restrict__ Ah,
                                                const __nv_bfloat16* __restrict__ Al,
                                                const __nv_bfloat16* __restrict__ Bh,
                                                const __nv_bfloat16* __restrict__ Bl,
                                                const float* __restrict__ bias,
                                                float* __restrict__ C,
                                                __nv_bfloat16* __restrict__ Ch,
                                                __nv_bfloat16* __restrict__ Cl,
                                                int mode, float scale)
{
    __shared__ __nv_bfloat16 sAh[128][SPAD];
    __shared__ __nv_bfloat16 sAl[128][SPAD];
    __shared__ __nv_bfloat16 sBh[128][SPAD];
    __shared__ __nv_bfloat16 sBl[128][SPAD];

    const int tid  = threadIdx.x;
    const int wid  = tid >> 5, lane = tid & 31;
    const int wm   = (wid >> 2) * 64;
    const int wn   = (wid & 3) * 32;
    const size_t row0 = (size_t)blockIdx.y * 128;
    const int    n0   = blockIdx.x * 128;

    float acc[4][4][4];
    #pragma unroll
    for (int mi = 0; mi < 4; ++mi)
        #pragma unroll
        for (int ni = 0; ni < 4; ++ni)
            #pragma unroll
            for (int e = 0; e < 4; ++e) acc[mi][ni][e] = 0.f;

    const int lrow = lane & 15, lcol = (lane >> 4) * 8;

    for (int k0 = 0; k0 < DD; k0 += 32) {
        __syncthreads();
        #pragma unroll
        for (int t = 0; t < 2; ++t) {
            int idx = tid + t*256;
            int r = idx >> 2, c = idx & 3;
            size_t ga = (row0 + r)*DD + k0 + c*8;
            size_t gb = (size_t)(n0 + r)*DD + k0 + c*8;
            *(uint4*)&sAh[r][c*8] = *(const uint4*)(Ah + ga);
            *(uint4*)&sAl[r][c*8] = *(const uint4*)(Al + ga);
            *(uint4*)&sBh[r][c*8] = *(const uint4*)(Bh + gb);
            *(uint4*)&sBl[r][c*8] = *(const uint4*)(Bl + gb);
        }
        __syncthreads();

        #pragma unroll
        for (int ks = 0; ks < 2; ++ks) {
            const int kb = ks*16 + lcol;
            uint32_t ah[4][4], al[4][4], bh[2][4], bl[2][4];
            #pragma unroll
            for (int mi = 0; mi < 4; ++mi) {
                ldm_x4(ah[mi], smem_u32(&sAh[wm + mi*16 + lrow][kb]));
                ldm_x4(al[mi], smem_u32(&sAl[wm + mi*16 + lrow][kb]));
            }
            #pragma unroll
            for (int g = 0; g < 2; ++g) {
                ldm_x4(bh[g], smem_u32(&sBh[wn + g*16 + lrow][kb]));
                ldm_x4(bl[g], smem_u32(&sBl[wn + g*16 + lrow][kb]));
            }
            #pragma unroll
            for (int mi = 0; mi < 4; ++mi)
                #pragma unroll
                for (int ni = 0; ni < 4; ++ni) {
                    const int g = ni >> 1, h = ni & 1;
                    mma_bf16(acc[mi][ni], ah[mi], bh[g][h], bh[g][h+2]);
                    mma_bf16(acc[mi][ni], ah[mi], bl[g][h], bl[g][h+2]);
                    mma_bf16(acc[mi][ni], al[mi], bh[g][h], bh[g][h+2]);
                }
        }
    }

    const int r_lo = lane >> 2, cpair = (lane & 3) * 2;
    if (mode == 0) {
        #pragma unroll
        for (int mi = 0; mi < 4; ++mi) {
            size_t rg0 = (row0 + wm + mi*16 + r_lo)*DD;
            size_t rg1 = rg0 + (size_t)8*DD;
            #pragma unroll
            for (int ni = 0; ni < 4; ++ni) {
                int col = n0 + wn + ni*8 + cpair;
                float v0 = (acc[mi][ni][0] + bias[col])   * scale;
                float v1 = (acc[mi][ni][1] + bias[col+1]) * scale;
                float v2 = (acc[mi][ni][2] + bias[col])   * scale;
                float v3 = (acc[mi][ni][3] + bias[col+1]) * scale;
                __nv_bfloat16 h0,h1,h2,h3,l0,l1,l2,l3;
                split_bf16(v0,h0,l0); split_bf16(v1,h1,l1);
                split_bf16(v2,h2,l2); split_bf16(v3,h3,l3);
                *(uint32_t*)(Ch + rg0 + col) = pack_bf2(h0,h1);
                *(uint32_t*)(Cl + rg0 + col) = pack_bf2(l0,l1);
                *(uint32_t*)(Ch + rg1 + col) = pack_bf2(h2,h3);
                *(uint32_t*)(Cl + rg1 + col) = pack_bf2(l2,l3);
            }
        }
    } else {
        #pragma unroll
        for (int mi = 0; mi < 4; ++mi) {
            size_t rg0 = row0 + wm + mi*16 + r_lo;
            size_t rg1 = rg0 + 8;
            int bp0 = (int)(rg0 >> 10), q0r = (int)(rg0 & 1023);
            float* crow0 = C + ((size_t)(((bp0>>1)*14 + (bp0&1))*1024 + q0r))*DD;
            int bp1 = (int)(rg1 >> 10); q0r = (int)(rg1 & 1023);
            float* crow1 = C + ((size_t)(((bp1>>1)*14 + (bp1&1))*1024 + q0r))*DD;
            #pragma unroll
            for (int ni = 0; ni < 4; ++ni) {
                int col = n0 + wn + ni*8 + cpair;
                *(float2*)(crow0 + col) = make_float2(acc[mi][ni][0] + bias[col], acc[mi][ni][1] + bias[col+1]);
                *(float2*)(crow1 + col) = make_float2(acc[mi][ni][2] + bias[col], acc[mi][ni][3] + bias[col+1]);
            }
        }
    }
}

/* ---- flash attention on mma.sync, split-bf16 x3 products.
       CTA: 128 q-rows, 8 warps x m16; 64-key tiles.
       grid (8 qtiles, 12 heads, 8 bp). Writes z fp32 + split bf16. ---- */
#define APAD 8
__global__ __launch_bounds__(256) void attn_mma()
{
    __shared__ __nv_bfloat16 sKh[64][64+APAD];
    __shared__ __nv_bfloat16 sKl[64][64+APAD];
    __shared__ __nv_bfloat16 sVh[64][64+APAD];
    __shared__ __nv_bfloat16 sVl[64][64+APAD];

    const int tid = threadIdx.x;
    const int w = tid >> 5, lane = tid & 31;
    const int qt = 7 - (int)blockIdx.x;          /* heavy tiles first */
    const int n  = blockIdx.y;
    const int bp = blockIdx.z;
    const int q0 = qt * 128;
    const int nkt = qt*2 + 2;

    const int lrow = lane & 15, lcol = (lane >> 4) * 8;
    const int r_lo = lane >> 2, cpair = (lane & 3) * 2;
    const int qrowA = q0 + w*16 + r_lo;          /* global q of row A */
    const int qrowB = qrowA + 8;

    /* load Q fragments (hi/lo) once, directly from global in frag layout */
    uint32_t aQh[4][4], aQl[4][4];
    {
        const __nv_bfloat16* qh = g_qh + (size_t)((size_t)bp*SS + qrowA)*DD + n*HDIM;
        const __nv_bfloat16* ql = g_ql + (size_t)((size_t)bp*SS + qrowA)*DD + n*HDIM;
        #pragma unroll
        for (int ks = 0; ks < 4; ++ks) {
            int c0 = ks*16 + cpair;
            aQh[ks][0] = *(const uint32_t*)(qh + c0);
            aQh[ks][1] = *(const uint32_t*)(qh + (size_t)8*DD + c0);
            aQh[ks][2] = *(const uint32_t*)(qh + c0 + 8);
            aQh[ks][3] = *(const uint32_t*)(qh + (size_t)8*DD + c0 + 8);
            aQl[ks][0] = *(const uint32_t*)(ql + c0);
            aQl[ks][1] = *(const uint32_t*)(ql + (size_t)8*DD + c0);
            aQl[ks][2] = *(const uint32_t*)(ql + c0 + 8);
            aQl[ks][3] = *(const uint32_t*)(ql + (size_t)8*DD + c0 + 8);
        }
    }

    float accz[8][4];
    #pragma unroll
    for (int t = 0; t < 8; ++t)
        #pragma unroll
        for (int e = 0; e < 4; ++e) accz[t][e] = 0.f;
    float m0 = -1e30f, m1 = -1e30f, L0 = 0.f, L1 = 0.f;

    const __nv_bfloat16* Kh = g_kh + (size_t)bp*SS*DD + n*HDIM;
    const __nv_bfloat16* Kl = g_kl + (size_t)bp*SS*DD + n*HDIM;
    const __nv_bfloat16* Vh = g_vh + (size_t)bp*SS*DD + n*HDIM;
    const __nv_bfloat16* Vl = g_vl + (size_t)bp*SS*DD + n*HDIM;

    for (int kt = 0; kt < nkt; ++kt) {
        const int k0 = kt * 64;
        __syncthreads();
        #pragma unroll
        for (int t = 0; t < 2; ++t) {
            int idx = tid + t*256;          /* 512 chunks: r=idx>>3, c=idx&7 */
            int r = idx >> 3, c = idx & 7;
            size_t g = (size_t)(k0 + r)*DD + c*8;
            *(uint4*)&sKh[r][c*8] = *(const uint4*)(Kh + g);
            *(uint4*)&sKl[r][c*8] = *(const uint4*)(Kl + g);
            *(uint4*)&sVh[r][c*8] = *(const uint4*)(Vh + g);
            *(uint4*)&sVl[r][c*8] = *(const uint4*)(Vl + g);
        }
        __syncthreads();

        /* S = Q K^T (64 keys), warp rows w*16.. */
        float s[8][4];
        #pragma unroll
        for (int t = 0; t < 8; ++t)
            #pragma unroll
            for (int e = 0; e < 4; ++e) s[t][e] = 0.f;
        #pragma unroll
        for (int ks = 0; ks < 4; ++ks) {
            #pragma unroll
            for (int g = 0; g < 4; ++g) {
                uint32_t bh[4], bl[4];
                ldm_x4(bh, smem_u32(&sKh[g*16 + lrow][ks*16 + lcol]));
                ldm_x4(bl, smem_u32(&sKl[g*16 + lrow][ks*16 + lcol]));
                #pragma unroll
                for (int h = 0; h < 2; ++h) {
                    float* acc = s[g*2 + h];
                    mma_bf16(acc, aQh[ks], bh[h], bh[h+2]);
                    mma_bf16(acc, aQh[ks], bl[h], bl[h+2]);
                    mma_bf16(acc, aQl[ks], bh[h], bh[h+2]);
                }
            }
        }

        /* causal mask: only last two k-tiles can cross the diagonal */
        if (kt >= nkt - 2) {
            #pragma unroll
            for (int t = 0; t < 8; ++t) {
                int key = k0 + t*8 + cpair;
                if (key   > qrowA) s[t][0] = -1e30f;
                if (key+1 > qrowA) s[t][1] = -1e30f;
                if (key   > qrowB) s[t][2] = -1e30f;
                if (key+1 > qrowB) s[t][3] = -1e30f;
            }
        }

        /* online softmax: rows A (e0,e1) / B (e2,e3), spread over 4 lanes */
        float mxA = -1e30f, mxB = -1e30f;
        #pragma unroll
        for (int t = 0; t < 8; ++t) {
            mxA = fmaxf(mxA, fmaxf(s[t][0], s[t][1]));
            mxB = fmaxf(mxB, fmaxf(s[t][2], s[t][3]));
        }
        mxA = fmaxf(mxA, __shfl_xor_sync(0xffffffffu, mxA, 1));
        mxA = fmaxf(mxA, __shfl_xor_sync(0xffffffffu, mxA, 2));
        mxB = fmaxf(mxB, __shfl_xor_sync(0xffffffffu, mxB, 1));
        mxB = fmaxf(mxB, __shfl_xor_sync(0xffffffffu, mxB, 2));
        float mn0 = fmaxf(m0, mxA), mn1 = fmaxf(m1, mxB);
        float al0 = __expf(m0 - mn0), al1 = __expf(m1 - mn1);
        m0 = mn0; m1 = mn1;

        float sumA = 0.f, sumB = 0.f;
        uint32_t aPh[4][4], aPl[4][4];
        #pragma unroll
        for (int ks = 0; ks < 4; ++ks) {
            #pragma unroll
            for (int half = 0; half < 2; ++half) {       /* S tiles 2ks, 2ks+1 */
                float* sv = s[2*ks + half];
                float p0 = __expf(sv[0] - mn0);
                float p1 = __expf(sv[1] - mn0);
                float p2 = __expf(sv[2] - mn1);
                float p3 = __expf(sv[3] - mn1);
                sumA += p0 + p1; sumB += p2 + p3;
                __nv_bfloat16 h0,h1,h2,h3,l0,l1,l2,l3;
                split_bf16(p0,h0,l0); split_bf16(p1,h1,l1);
                split_bf16(p2,h2,l2); split_bf16(p3,h3,l3);
                aPh[ks][0 + 2*half] = pack_bf2(h0,h1);
                aPh[ks][1 + 2*half] = pack_bf2(h2,h3);
                aPl[ks][0 + 2*half] = pack_bf2(l0,l1);
                aPl[ks][1 + 2*half] = pack_bf2(l2,l3);
            }
        }
        sumA += __shfl_xor_sync(0xffffffffu, sumA, 1);
        sumA += __shfl_xor_sync(0xffffffffu, sumA, 2);
        sumB += __shfl_xor_sync(0xffffffffu, sumB, 1);
        sumB += __shfl_xor_sync(0xffffffffu, sumB, 2);
        L0 = L0*al0 + sumA;
        L1 = L1*al1 + sumB;

        /* rescale accumulators */
        #pragma unroll
        for (int t = 0; t < 8; ++t) {
            accz[t][0] *= al0; accz[t][1] *= al0;
            accz[t][2] *= al1; accz[t][3] *= al1;
        }

        /* z += P @ V ; V via trans ldmatrix: n8-tile h -> regs 2h, 2h+1 */
        #pragma unroll
        for (int ks = 0; ks < 4; ++ks) {
            #pragma unroll
            for (int g = 0; g < 4; ++g) {
                uint32_t bh[4], bl[4];
                ldm_x4_t(bh, smem_u32(&sVh[ks*16 + lrow][g*16 + lcol]));
                ldm_x4_t(bl, smem_u32(&sVl[ks*16 + lrow][g*16 + lcol]));
                #pragma unroll
                for (int h = 0; h < 2; ++h) {
                    float* acc = accz[g*2 + h];
                    mma_bf16(acc, aPh[ks], bh[2*h], bh[2*h+1]);
                    mma_bf16(acc, aPh[ks], bl[2*h], bl[2*h+1]);
                    mma_bf16(acc, aPl[ks], bh[2*h], bh[2*h+1]);
                }
            }
        }
    }

    /* epilogue: z/L -> fp32 g_z and split bf16 g_zh/g_zl */
    float inv0 = 1.0f / L0, inv1 = 1.0f / L1;
    size_t rowA = (size_t)bp*SS + qrowA;
    size_t offA = rowA*DD + n*HDIM;
    size_t offB = offA + (size_t)8*DD;
    #pragma unroll
    for (int t = 0; t < 8; ++t) {
        int col = t*8 + cpair;
        float z0 = accz[t][0]*inv0, z1 = accz[t][1]*inv0;
        float z2 = accz[t][2]*inv1, z3 = accz[t][3]*inv1;
        *(float2*)(g_z + offA + col) = make_float2(z0, z1);
        *(float2*)(g_z + offB + col) = make_float2(z2, z3);
        __nv_bfloat16 h0,h1,h2,h3,l0,l1,l2,l3;
        split_bf16(z0,h0,l0); split_bf16(z1,h1,l1);
        split_bf16(z2,h2,l2); split_bf16(z3,h3,l3);
        *(uint32_t*)(g_zh + offA + col) = pack_bf2(h0,h1);
        *(uint32_t*)(g_zl + offA + col) = pack_bf2(l0,l1);
        *(uint32_t*)(g_zh + offB + col) = pack_bf2(h2,h3);
        *(uint32_t*)(g_zl + offB + col) = pack_bf2(l2,l3);
    }
}

/* ---- per-head delta GEMM (FFMA2, unchanged) ---- */
__global__ __launch_bounds__(256) void delta_kernel(const float* __restrict__ Wo,
                                                    float* __restrict__ out)
{
    __shared__ float As[16][132];
    __shared__ float Bs[16][128];

    const int tid = threadIdx.x;
    const int tx = tid & 15, ty = tid >> 4;
    const int head = blockIdx.z;
    const size_t row0 = (size_t)blockIdx.y * 128;
    const int    col0 = blockIdx.x * 128;
    const int b = (int)(row0 >> 10);
    const float* Bm = Wo + (size_t)head * HDIM * DD;

    u64 acc[8][4];
    #pragma unroll
    for (int i = 0; i < 8; ++i)
        #pragma unroll
        for (int j = 0; j < 4; ++j) acc[i][j] = 0ull;

    const int ar = tid >> 2;
    const int ak = (tid & 3) * 4;
    const int bk = tid >> 5;
    const int bc = (tid & 31) * 4;

    for (int k0 = 0; k0 < HDIM; k0 += 16) {
        int q = ((int)row0 + ar) & 1023;
        size_t z0 = ((size_t)(b*2 + 0)*SS + q)*DD + head*HDIM + k0 + ak;
        size_t z1 = ((size_t)(b*2 + 1)*SS + q)*DD + head*HDIM + k0 + ak;
        float4 p0  = *(const float4*)(g_z + z0);
        float4 p1  = *(const float4*)(g_z + z1);
        float4 p0b = *(const float4*)(g_z + z0 + (size_t)64*DD);
        float4 p1b = *(const float4*)(g_z + z1 + (size_t)64*DD);
        float4 a0 = make_float4(p0.x-p1.x,   p0.y-p1.y,   p0.z-p1.z,   p0.w-p1.w);
        float4 a1 = make_float4(p0b.x-p1b.x, p0b.y-p1b.y, p0b.z-p1b.z, p0b.w-p1b.w);
        float4 b0 = *(const float4*)(Bm + (size_t)(k0 + bk    )*DD + col0 + bc);
        float4 b1 = *(const float4*)(Bm + (size_t)(k0 + bk + 8)*DD + col0 + bc);
        __syncthreads();
        As[ak+0][ar]    = a0.x; As[ak+1][ar]    = a0.y; As[ak+2][ar]    = a0.z; As[ak+3][ar]    = a0.w;
        As[ak+0][ar+64] = a1.x; As[ak+1][ar+64] = a1.y; As[ak+2][ar+64] = a1.z; As[ak+3][ar+64] = a1.w;
        *(float4*)&Bs[bk  ][bc] = b0;
        *(float4*)&Bs[bk+8][bc] = b1;
        __syncthreads();
        #pragma unroll
        for (int kk = 0; kk < 16; ++kk) {
            float4 av0 = *(const float4*)&As[kk][ty*8];
            float4 av1 = *(const float4*)&As[kk][ty*8+4];
            float4 bv0 = *(const float4*)&Bs[kk][tx*8];
            float4 bv1 = *(const float4*)&Bs[kk][tx*8+4];
            u64 bb0 = pack2(bv0.x, bv0.y), bb1 = pack2(bv0.z, bv0.w);
            u64 bb2 = pack2(bv1.x, bv1.y), bb3 = pack2(bv1.z, bv1.w);
            float av[8] = {av0.x,av0.y,av0.z,av0.w,av1.x,av1.y,av1.z,av1.w};
            #pragma unroll
            for (int i = 0; i < 8; ++i) {
                u64 ad = dup2(av[i]);
                fma2(acc[i][0], ad, bb0);
                fma2(acc[i][1], ad, bb1);
                fma2(acc[i][2], ad, bb2);
                fma2(acc[i][3], ad, bb3);
            }
        }
    }

    #pragma unroll
    for (int i = 0; i < 8; ++i) {
        int q = ((int)row0 + ty*8 + i) & 1023;
        const float* base = out + ((size_t)(b*14 + 1)*SS + q)*DD + col0 + tx*8;
        float*       dst  = out + ((size_t)(b*14 + 2 + head)*SS + q)*DD + col0 + tx*8;
        float o[8];
        unpack2(acc[i][0], o[0], o[1]); unpack2(acc[i][1], o[2], o[3]);
        unpack2(acc[i][2], o[4], o[5]); unpack2(acc[i][3], o[6], o[7]);
        float4 b0 = *(const float4*)(base);
        float4 b1 = *(const float4*)(base + 4);
        *(float4*)(dst)     = make_float4(b0.x+o[0], b0.y+o[1], b0.z+o[2], b0.w+o[3]);
        *(float4*)(dst + 4) = make_float4(b1.x+o[4], b1.y+o[5], b1.z+o[6], b1.w+o[7]);
    }
}

extern "C" void kernel_launch(void* const* d_in, const int* in_sizes, int n_in,
                              void* d_out, int out_size)
{
    const float* x0 = (const float*)d_in[0];
    const float* x1 = (const float*)d_in[1];
    const float* WQ = (const float*)d_in[2];
    const float* bQ = (const float*)d_in[3];
    const float* WK = (const float*)d_in[4];
    const float* bK = (const float*)d_in[5];
    const float* WV = (const float*)d_in[6];
    const float* bV = (const float*)d_in[7];
    const float* WO = (const float*)d_in[8];
    const float* bO = (const float*)d_in[9];
    float* out = (float*)d_out;

    __nv_bfloat16 *gxh, *gxl, *gqh, *gql, *gkh, *gkl, *gvh, *gvl, *gzh, *gzl;
    __nv_bfloat16 *gwth, *gwtl, *gwoth, *gwotl;
    cudaGetSymbolAddress((void**)&gxh,  g_xh);
    cudaGetSymbolAddress((void**)&gxl,  g_xl);
    cudaGetSymbolAddress((void**)&gqh,  g_qh);
    cudaGetSymbolAddress((void**)&gql,  g_ql);
    cudaGetSymbolAddress((void**)&gkh,  g_kh);
    cudaGetSymbolAddress((void**)&gkl,  g_kl);
    cudaGetSymbolAddress((void**)&gvh,  g_vh);
    cudaGetSymbolAddress((void**)&gvl,  g_vl);
    cudaGetSymbolAddress((void**)&gzh,  g_zh);
    cudaGetSymbolAddress((void**)&gzl,  g_zl);
    cudaGetSymbolAddress((void**)&gwth, g_wth);
    cudaGetSymbolAddress((void**)&gwtl, g_wtl);
    cudaGetSymbolAddress((void**)&gwoth, g_woth);
    cudaGetSymbolAddress((void**)&gwotl, g_wotl);

    pack_x_kernel  <<<RR*DD/4/256, 256>>>(x0, x1);
    repack_w_kernel<<<DD*DD/256,   256>>>(WQ, WK, WV, WO);

    dim3 gproj(DD/128, RR/128);     /* (6, 64) */
    gemm_mma<<<gproj, 256>>>(gxh, gxl, gwth,           gwtl,           bQ, nullptr, gqh, gql, 0, 0.125f);
    gemm_mma<<<gproj, 256>>>(gxh, gxl, gwth + DD*DD,   gwtl + DD*DD,   bK, nullptr, gkh, gkl, 0, 1.0f);
    gemm_mma<<<gproj, 256>>>(gxh, gxl, gwth + 2*DD*DD, gwtl + 2*DD*DD, bV, nullptr, gvh, gvl, 0, 1.0f);

    attn_mma<<<dim3(8, NHEADS, BB*PP), 256>>>();

    gemm_mma<<<gproj, 256>>>(gzh, gzl, gwoth, gwotl, bO, out, nullptr, nullptr, 1, 1.0f);

    delta_kernel<<<dim3(DD/128, BB*SS/128, NHEADS), 256>>>(WO, out);
}